// round 14
// baseline (speedup 1.0000x reference)
#include <cuda_runtime.h>
#include <cuda_fp16.h>
#include <stdint.h>

#define NB 512
#define PL 200
#define PLC 100
#define QL 60
#define QE 260
#define DIM 512
#define NT 256
#define MST 36        // u32 stride of fp16-pair part arrays (144B rows, LDSM conflict-free)
#define EPST 132
#define QSTB 272      // Q buffer row stride in bytes (136 fp16) — trans-LDSM conflict-free

// ---- smem layout (byte offsets) ----
#define SM_RED   0
#define SM_MALL  128
#define SM_WP    1152
#define SM_QV    2176
#define SM_QR    4224
#define SM_PMAX  6272
#define SM_PSUM  7296
#define SM_MLOC  8320
#define AW0_OFF  8960     // u32[128][36]: A-hi -> W-hi
#define AW1_OFF  27392    // u32[128][36]: A-lo -> W-lo
#define Q0_OFF   45824    // u16[64][136]: qry k-major (rn-rounded fp16, GEMM2)
#define B0_OFF   45824    // u32[64][36] GEMM1 B-hi (aliases Q0, dead before GEMM2)
#define B1_OFF   55040    // GEMM1 B-lo (ends 64256)
#define EP_OFF   64512    // f32[32][132] epilogue bounce
#define SMEM_BYTES 81408

// fast fp32 -> fp16 hi/lo split: truncate mantissa to 10 bits (exact in fp16),
// residual lo = f - hi is exact in fp32; one f16x2 cvt packs a pair.
__device__ __forceinline__ float hif(float f) {
    return __uint_as_float(__float_as_uint(f) & 0xFFFFE000u);
}
__device__ __forceinline__ uint32_t pk2h(float lo, float hi) {
    uint32_t r;
    asm("cvt.rn.f16x2.f32 %0, %1, %2;" : "=r"(r) : "f"(hi), "f"(lo));
    return r;
}
__device__ __forceinline__ void cvt4(float4 v, uint32_t& h01, uint32_t& h23,
                                     uint32_t& l01, uint32_t& l23) {
    float hx = hif(v.x), hy = hif(v.y), hz = hif(v.z), hw = hif(v.w);
    h01 = pk2h(hx, hy);
    h23 = pk2h(hz, hw);
    l01 = pk2h(v.x - hx, v.y - hy);
    l23 = pk2h(v.z - hz, v.w - hw);
}
__device__ __forceinline__ void mma16816(float* d, const uint32_t* a, const uint32_t* b) {
    asm volatile(
        "mma.sync.aligned.m16n8k16.row.col.f32.f16.f16.f32 "
        "{%0,%1,%2,%3}, {%4,%5,%6,%7}, {%8,%9}, {%0,%1,%2,%3};"
        : "+f"(d[0]), "+f"(d[1]), "+f"(d[2]), "+f"(d[3])
        : "r"(a[0]), "r"(a[1]), "r"(a[2]), "r"(a[3]), "r"(b[0]), "r"(b[1]));
}
__device__ __forceinline__ void ldsm4(uint32_t& r0, uint32_t& r1, uint32_t& r2,
                                      uint32_t& r3, uint32_t addr) {
    asm volatile("ldmatrix.sync.aligned.m8n8.x4.shared.b16 {%0,%1,%2,%3}, [%4];"
                 : "=r"(r0), "=r"(r1), "=r"(r2), "=r"(r3) : "r"(addr));
}
__device__ __forceinline__ void ldsm4t(uint32_t& r0, uint32_t& r1, uint32_t& r2,
                                       uint32_t& r3, uint32_t addr) {
    asm volatile("ldmatrix.sync.aligned.m8n8.x4.trans.shared.b16 {%0,%1,%2,%3}, [%4];"
                 : "=r"(r0), "=r"(r1), "=r"(r2), "=r"(r3) : "r"(addr));
}
__device__ __forceinline__ uint32_t ctarank() {
    uint32_t r; asm("mov.u32 %0, %%cluster_ctarank;" : "=r"(r)); return r;
}
__device__ __forceinline__ uint32_t mapa_sh(uint32_t a, uint32_t rk) {
    uint32_t o; asm("mapa.shared::cluster.u32 %0, %1, %2;" : "=r"(o) : "r"(a), "r"(rk));
    return o;
}
__device__ __forceinline__ void st_remote_f32(uint32_t a, float v) {
    asm volatile("st.shared::cluster.f32 [%0], %1;" :: "r"(a), "f"(v) : "memory");
}
__device__ __forceinline__ void st_remote_f32x2(uint32_t a, float v0, float v1) {
    asm volatile("st.shared::cluster.v2.f32 [%0], {%1, %2};"
                 :: "r"(a), "f"(v0), "f"(v1) : "memory");
}
#define CLUSTER_SYNC() do { \
    asm volatile("barrier.cluster.arrive.aligned;" ::: "memory"); \
    asm volatile("barrier.cluster.wait.aligned;" ::: "memory"); } while (0)

__global__ void __launch_bounds__(NT, 2) __cluster_dims__(2, 1, 1)
ce_hmma14(const float* __restrict__ enc, float* __restrict__ out)
{
    extern __shared__ char smc[];
    float* red   = (float*)(smc + SM_RED);
    float* m_all = (float*)(smc + SM_MALL);
    float* wp    = (float*)(smc + SM_WP);
    float* qvec  = (float*)(smc + SM_QV);
    float* qrecv = (float*)(smc + SM_QR);
    float* pmax  = (float*)(smc + SM_PMAX);
    float* psum  = (float*)(smc + SM_PSUM);
    float* m_loc = (float*)(smc + SM_MLOC);
    uint32_t* AW0 = (uint32_t*)(smc + AW0_OFF);
    uint32_t* AW1 = (uint32_t*)(smc + AW1_OFF);
    uint32_t* B0s = (uint32_t*)(smc + B0_OFF);
    uint32_t* B1s = (uint32_t*)(smc + B1_OFF);
    float* EP  = (float*)(smc + EP_OFF);

    uint32_t sm0;
    { uint64_t t = __cvta_generic_to_shared(smc); sm0 = (uint32_t)t; }

    const int tid  = threadIdx.x;
    const int lane = tid & 31;
    const int warp = tid >> 5;
    const int lq   = lane & 3;
    const int lr   = lane >> 2;
    const int b    = blockIdx.x >> 1;
    const uint32_t rank = ctarank();
    const int p_base = (int)rank * PLC;

    const float* enc_b = enc + (size_t)b * QE * DIM;
    const float* arow_g = enc_b + (size_t)p_base * DIM;
    const float* qry_g  = enc_b + (size_t)PL * DIM;

    const int wm = warp >> 1, wn = warp & 1;
    const int m0 = wm * 32, n0 = wn * 32;

    // ldmatrix per-thread address offsets
    const uint32_t lA = (uint32_t)((((lane >> 3) & 1) * 8 + (lane & 7)) * 144
                                   + ((lane >> 4) * 8) * 2);
    const uint32_t lB = (uint32_t)((((lane >> 4) << 3) + (lane & 7)) * 144
                                   + (((lane >> 3) & 1) * 8) * 2);
    // trans-LDSM lane map for k-major Q
    const uint32_t lT = (uint32_t)(((lane & 7) + ((lane >> 3) & 1) * 8) * QSTB
                                   + (lane >> 4) * 16);
    const uint32_t aA0 = sm0 + AW0_OFF + (uint32_t)(m0 * 144) + lA;
    const uint32_t aA1 = sm0 + AW1_OFF + (uint32_t)(m0 * 144) + lA;
    const uint32_t aB0g1 = sm0 + B0_OFF + (uint32_t)(n0 * 144) + lB;
    const uint32_t aB1g1 = sm0 + B1_OFF + (uint32_t)(n0 * 144) + lB;
    const uint32_t aQ0 = sm0 + Q0_OFF + (uint32_t)(wn * 64 * 2) + lT;

    // ================= GEMM1: sim[128x64] = A @ qry^T, K=512 =================
    float4 pa[8], pb[4];
    #pragma unroll
    for (int k = 0; k < 8; k++) {
        int idx = tid + 256 * k, r = idx >> 4, c4 = idx & 15;
        pa[k] = *(const float4*)&arow_g[(size_t)r * DIM + c4 * 4];
    }
    #pragma unroll
    for (int k = 0; k < 4; k++) {
        int idx = tid + 256 * k, q = idx >> 4, c4 = idx & 15;
        pb[k] = (q < QL) ? *(const float4*)&qry_g[(size_t)q * DIM + c4 * 4]
                         : make_float4(0.f, 0.f, 0.f, 0.f);
    }

    float acc[2][4][4];
    #pragma unroll
    for (int i = 0; i < 2; i++)
        #pragma unroll
        for (int j = 0; j < 4; j++)
            #pragma unroll
            for (int k = 0; k < 4; k++) acc[i][j][k] = 0.f;

    for (int ch = 0; ch < 8; ch++) {
        #pragma unroll
        for (int k = 0; k < 8; k++) {
            int idx = tid + 256 * k, r = idx >> 4, c4 = idx & 15;
            uint32_t h01, h23, l01, l23;
            cvt4(pa[k], h01, h23, l01, l23);
            int o = r * MST + c4 * 2;
            AW0[o] = h01; AW0[o + 1] = h23;
            AW1[o] = l01; AW1[o + 1] = l23;
        }
        #pragma unroll
        for (int k = 0; k < 4; k++) {
            int idx = tid + 256 * k, q = idx >> 4, c4 = idx & 15;
            uint32_t h01, h23, l01, l23;
            cvt4(pb[k], h01, h23, l01, l23);
            int o = q * MST + c4 * 2;
            B0s[o] = h01; B0s[o + 1] = h23;
            B1s[o] = l01; B1s[o + 1] = l23;
        }
        __syncthreads();

        if (ch < 7) {
            const int d0 = (ch + 1) * 64;
            #pragma unroll
            for (int k = 0; k < 8; k++) {
                int idx = tid + 256 * k, r = idx >> 4, c4 = idx & 15;
                pa[k] = *(const float4*)&arow_g[(size_t)r * DIM + d0 + c4 * 4];
            }
            #pragma unroll
            for (int k = 0; k < 4; k++) {
                int idx = tid + 256 * k, q = idx >> 4, c4 = idx & 15;
                pb[k] = (q < QL) ? *(const float4*)&qry_g[(size_t)q * DIM + d0 + c4 * 4]
                                 : make_float4(0.f, 0.f, 0.f, 0.f);
            }
        }

        #pragma unroll
        for (int ks = 0; ks < 4; ks++) {
            uint32_t bh[4][2], bl[4][2];
            #pragma unroll
            for (int pp = 0; pp < 2; pp++) {
                ldsm4(bh[2*pp][0], bh[2*pp][1], bh[2*pp+1][0], bh[2*pp+1][1],
                      aB0g1 + pp * (16 * 144) + ks * 32);
                ldsm4(bl[2*pp][0], bl[2*pp][1], bl[2*pp+1][0], bl[2*pp+1][1],
                      aB1g1 + pp * (16 * 144) + ks * 32);
            }
            #pragma unroll
            for (int mt = 0; mt < 2; mt++) {
                uint32_t ah[4], al[4];
                ldsm4(ah[0], ah[1], ah[2], ah[3], aA0 + mt * (16 * 144) + ks * 32);
                ldsm4(al[0], al[1], al[2], al[3], aA1 + mt * (16 * 144) + ks * 32);
                #pragma unroll
                for (int nt = 0; nt < 4; nt++) {
                    mma16816(acc[mt][nt], ah, bh[nt]);
                    mma16816(acc[mt][nt], ah, bl[nt]);
                    mma16816(acc[mt][nt], al, bh[nt]);
                }
            }
        }
        __syncthreads();
    }

    // ---- stage Q(dch=0) now (Q aliases dead B stage); LDG latency hides under softmax ----
    #pragma unroll
    for (int k = 0; k < 8; k++) {
        int idx = tid + 256 * k, q = idx >> 5, c4 = idx & 31;
        float4 v = (q < QL) ? *(const float4*)&qry_g[(size_t)q * DIM + c4 * 4]
                            : make_float4(0.f, 0.f, 0.f, 0.f);
        uint32_t* p0 = (uint32_t*)(smc + Q0_OFF + q * QSTB + c4 * 8);
        p0[0] = pk2h(v.x, v.y);
        p0[1] = pk2h(v.z, v.w);
    }

    // ====== fragment-resident softmax over q; W -> AW0/AW1 as fp16 hi/lo ======
    {
        float mx[2][2];
        #pragma unroll
        for (int mt = 0; mt < 2; mt++) { mx[mt][0] = -3.4e38f; mx[mt][1] = -3.4e38f; }
        #pragma unroll
        for (int mt = 0; mt < 2; mt++)
            #pragma unroll
            for (int nt = 0; nt < 4; nt++) {
                int col = n0 + nt * 8 + lq * 2;
                if (col < QL) {
                    mx[mt][0] = fmaxf(mx[mt][0], acc[mt][nt][0]);
                    mx[mt][1] = fmaxf(mx[mt][1], acc[mt][nt][2]);
                }
                if (col + 1 < QL) {
                    mx[mt][0] = fmaxf(mx[mt][0], acc[mt][nt][1]);
                    mx[mt][1] = fmaxf(mx[mt][1], acc[mt][nt][3]);
                }
            }
        #pragma unroll
        for (int mt = 0; mt < 2; mt++)
            #pragma unroll
            for (int rh = 0; rh < 2; rh++) {
                mx[mt][rh] = fmaxf(mx[mt][rh], __shfl_xor_sync(0xffffffffu, mx[mt][rh], 1));
                mx[mt][rh] = fmaxf(mx[mt][rh], __shfl_xor_sync(0xffffffffu, mx[mt][rh], 2));
            }
        if (lq == 0) {
            #pragma unroll
            for (int mt = 0; mt < 2; mt++)
                #pragma unroll
                for (int rh = 0; rh < 2; rh++)
                    pmax[wn * 128 + m0 + mt * 16 + rh * 8 + lr] = mx[mt][rh];
        }
        __syncthreads();
        float fmx[2][2];
        #pragma unroll
        for (int mt = 0; mt < 2; mt++)
            #pragma unroll
            for (int rh = 0; rh < 2; rh++) {
                int row = m0 + mt * 16 + rh * 8 + lr;
                fmx[mt][rh] = fmaxf(pmax[row], pmax[128 + row]);
                if (wn == 0 && lq == 0) m_loc[row] = fmx[mt][rh];
            }
        float sm[2][2];
        #pragma unroll
        for (int mt = 0; mt < 2; mt++) { sm[mt][0] = 0.f; sm[mt][1] = 0.f; }
        #pragma unroll
        for (int mt = 0; mt < 2; mt++)
            #pragma unroll
            for (int nt = 0; nt < 4; nt++) {
                int col = n0 + nt * 8 + lq * 2;
                float e0 = (col     < QL) ? expf(acc[mt][nt][0] - fmx[mt][0]) : 0.f;
                float e1 = (col + 1 < QL) ? expf(acc[mt][nt][1] - fmx[mt][0]) : 0.f;
                float e2 = (col     < QL) ? expf(acc[mt][nt][2] - fmx[mt][1]) : 0.f;
                float e3 = (col + 1 < QL) ? expf(acc[mt][nt][3] - fmx[mt][1]) : 0.f;
                acc[mt][nt][0] = e0; acc[mt][nt][1] = e1;
                acc[mt][nt][2] = e2; acc[mt][nt][3] = e3;
                sm[mt][0] += e0 + e1; sm[mt][1] += e2 + e3;
            }
        #pragma unroll
        for (int mt = 0; mt < 2; mt++)
            #pragma unroll
            for (int rh = 0; rh < 2; rh++) {
                sm[mt][rh] += __shfl_xor_sync(0xffffffffu, sm[mt][rh], 1);
                sm[mt][rh] += __shfl_xor_sync(0xffffffffu, sm[mt][rh], 2);
            }
        if (lq == 0) {
            #pragma unroll
            for (int mt = 0; mt < 2; mt++)
                #pragma unroll
                for (int rh = 0; rh < 2; rh++)
                    psum[wn * 128 + m0 + mt * 16 + rh * 8 + lr] = sm[mt][rh];
        }
        __syncthreads();
        #pragma unroll
        for (int mt = 0; mt < 2; mt++) {
            float inv0, inv1;
            {
                int r0 = m0 + mt * 16 + lr;
                inv0 = 1.f / (psum[r0] + psum[128 + r0]);
                inv1 = 1.f / (psum[r0 + 8] + psum[128 + r0 + 8]);
            }
            #pragma unroll
            for (int nt = 0; nt < 4; nt++) {
                int cw = wn * 16 + nt * 4 + lq;
                int r0 = (m0 + mt * 16 + lr) * MST;
                int r1 = r0 + 8 * MST;
                float wa = acc[mt][nt][0] * inv0, wb = acc[mt][nt][1] * inv0;
                float ha = hif(wa), hb = hif(wb);
                AW0[r0 + cw] = pk2h(ha, hb);
                AW1[r0 + cw] = pk2h(wa - ha, wb - hb);
                float wc = acc[mt][nt][2] * inv1, wd = acc[mt][nt][3] * inv1;
                float hc = hif(wc), hd = hif(wd);
                AW0[r1 + cw] = pk2h(hc, hd);
                AW1[r1 + cw] = pk2h(wc - hc, wd - hd);
            }
        }
    }
    __syncthreads();

    // ====== exchange per-row maxes with partner CTA (DSMEM) ======
    if (tid < PLC) {
        float v = m_loc[tid];
        m_all[p_base + tid] = v;
        st_remote_f32(mapa_sh(sm0 + SM_MALL + (uint32_t)(p_base + tid) * 4, rank ^ 1u), v);
    }
    CLUSTER_SYNC();

    // ====== softmax over p of max_sim -> wp[200] ======
    {
        float v = (tid < PL) ? m_all[tid] : -3.4e38f;
        float mv = v;
        #pragma unroll
        for (int o = 16; o > 0; o >>= 1) mv = fmaxf(mv, __shfl_xor_sync(0xffffffffu, mv, o));
        if (lane == 0) red[warp] = mv;
        __syncthreads();
        if (warp == 0) {
            float x = (lane < 8) ? red[lane] : -3.4e38f;
            #pragma unroll
            for (int o = 4; o > 0; o >>= 1) x = fmaxf(x, __shfl_xor_sync(0xffffffffu, x, o));
            if (lane == 0) red[8] = x;
        }
        __syncthreads();
        float gmax = red[8];
        float e = (tid < PL) ? expf(v - gmax) : 0.f;
        float sv = e;
        #pragma unroll
        for (int o = 16; o > 0; o >>= 1) sv += __shfl_xor_sync(0xffffffffu, sv, o);
        if (lane == 0) red[16 + warp] = sv;
        __syncthreads();
        if (warp == 0) {
            float x = (lane < 8) ? red[16 + lane] : 0.f;
            #pragma unroll
            for (int o = 4; o > 0; o >>= 1) x += __shfl_xor_sync(0xffffffffu, x, o);
            if (lane == 0) red[9] = x;
        }
        __syncthreads();
        if (tid < PL) wp[tid] = e / red[9];
    }
    __syncthreads();

    // ====== partial q2c over own 100 rows (float2/thread); exchange; qvec = sum ======
    {
        float2 qa = make_float2(0.f, 0.f);
        #pragma unroll 4
        for (int i = 0; i < PLC; i++) {
            float w = wp[p_base + i];
            float2 a = *(const float2*)&arow_g[(size_t)i * DIM + 2 * tid];
            qa.x += w * a.x;
            qa.y += w * a.y;
        }
        st_remote_f32x2(mapa_sh(sm0 + SM_QR + (uint32_t)(2 * tid) * 4, rank ^ 1u),
                        qa.x, qa.y);
        CLUSTER_SYNC();
        qvec[2 * tid]     = qa.x + qrecv[2 * tid];
        qvec[2 * tid + 1] = qa.y + qrecv[2 * tid + 1];
    }
    __syncthreads();

    // ================= GEMM2: c2q = W @ qry + epilogue (4 d-chunks) =================
    // 2-term decomposition: (W_hi + W_lo) @ qry_fp16(rn). Q(dch) staged ahead of time:
    // dch=0 staged after GEMM1; dch+1 staged inside dch's epilogue (g=0, post-publish).
    const float4* ctx4 = (const float4*)enc_b;
    const float4* qv4  = (const float4*)qvec;
    float4* out4 = (float4*)out + (size_t)b * PL * 512;

    #pragma unroll 1
    for (int dch = 0; dch < 4; dch++) {
        // ---- MMA: [128 p] x [128 d], K=64 (q); B via trans-LDSM, 2 terms ----
        float a2[2][8][4];
        #pragma unroll
        for (int i = 0; i < 2; i++)
            #pragma unroll
            for (int j = 0; j < 8; j++)
                #pragma unroll
                for (int k = 0; k < 4; k++) a2[i][j][k] = 0.f;

        #pragma unroll
        for (int ks = 0; ks < 4; ks++) {
            uint32_t ah[2][4], al[2][4];
            #pragma unroll
            for (int mt = 0; mt < 2; mt++) {
                ldsm4(ah[mt][0], ah[mt][1], ah[mt][2], ah[mt][3],
                      aA0 + mt * (16 * 144) + ks * 32);
                ldsm4(al[mt][0], al[mt][1], al[mt][2], al[mt][3],
                      aA1 + mt * (16 * 144) + ks * 32);
            }
            #pragma unroll
            for (int pp = 0; pp < 4; pp++) {
                uint32_t bh[2][2];
                ldsm4t(bh[0][0], bh[0][1], bh[1][0], bh[1][1],
                       aQ0 + ks * (16 * QSTB) + pp * 32);
                #pragma unroll
                for (int h = 0; h < 2; h++) {
                    int nt = pp * 2 + h;
                    #pragma unroll
                    for (int mt = 0; mt < 2; mt++) {
                        mma16816(a2[mt][nt], ah[mt], bh[h]);
                        mma16816(a2[mt][nt], al[mt], bh[h]);
                    }
                }
            }
        }

        // ---- epilogue: 4 groups of 32 p-rows; Q(dch+1) staged during g=0 ----
        #pragma unroll 1
        for (int g = 0; g < 4; g++) {
            __syncthreads();   // also guarantees all MMA Q-reads done before restage
            if (wm == g) {
                #pragma unroll
                for (int mt = 0; mt < 2; mt++)
                    #pragma unroll
                    for (int nt = 0; nt < 8; nt++) {
                        int col = wn * 64 + nt * 8 + lq * 2;
                        *(float2*)&EP[(mt * 16 + lr) * EPST + col] =
                            make_float2(a2[mt][nt][0], a2[mt][nt][1]);
                        *(float2*)&EP[(mt * 16 + lr + 8) * EPST + col] =
                            make_float2(a2[mt][nt][2], a2[mt][nt][3]);
                    }
            }
            __syncthreads();
            if (g == 0 && dch < 3) {
                // restage Q for next dch; overlaps with drain below (visible via g=1..3 syncs)
                const int d0 = (dch + 1) * 128;
                #pragma unroll
                for (int k = 0; k < 8; k++) {
                    int idx = tid + 256 * k, q = idx >> 5, c4 = idx & 31;
                    float4 v = (q < QL)
                        ? *(const float4*)&qry_g[(size_t)q * DIM + d0 + c4 * 4]
                        : make_float4(0.f, 0.f, 0.f, 0.f);
                    uint32_t* p0 = (uint32_t*)(smc + Q0_OFF + q * QSTB + c4 * 8);
                    p0[0] = pk2h(v.x, v.y);
                    p0[1] = pk2h(v.z, v.w);
                }
            }
            #pragma unroll
            for (int j = 0; j < 4; j++) {
                int p_loc = g * 32 + warp * 4 + j;
                if (p_loc < PLC) {
                    int p = p_base + p_loc;
                    int d4 = dch * 32 + lane;
                    float4 cq = *(const float4*)&EP[(warp * 4 + j) * EPST + lane * 4];
                    float4 c  = ctx4[(size_t)p * 128 + d4];
                    float4 qc = qv4[d4];
                    float4* ob = out4 + (size_t)p * 512 + d4;
                    __stcs(ob,       c);
                    __stcs(ob + 128, cq);
                    __stcs(ob + 256, make_float4(c.x * cq.x, c.y * cq.y,
                                                 c.z * cq.z, c.w * cq.w));
                    __stcs(ob + 384, make_float4(c.x * qc.x, c.y * qc.y,
                                                 c.z * qc.z, c.w * qc.w));
                }
            }
        }
    }
}

extern "C" void kernel_launch(void* const* d_in, const int* in_sizes, int n_in,
                              void* d_out, int out_size)
{
    const float* enc = (const float*)d_in[0];
    float* out = (float*)d_out;
    cudaFuncSetAttribute(ce_hmma14,
                         cudaFuncAttributeMaxDynamicSharedMemorySize, SMEM_BYTES);
    ce_hmma14<<<NB * 2, NT, SMEM_BYTES>>>(enc, out);
}

// round 15
// speedup vs baseline: 1.1090x; 1.1090x over previous
#include <cuda_runtime.h>
#include <cuda_fp16.h>
#include <stdint.h>

#define NB 512
#define PL 200
#define PLC 100
#define QL 60
#define QE 260
#define DIM 512
#define NT 256
#define MST 36        // u32 stride of fp16-pair part arrays (144B rows, LDSM conflict-free)
#define EPST 132
#define QSTB 272      // Q buffer row stride in bytes (136 fp16) — trans-LDSM conflict-free

// ---- smem layout (byte offsets) ----
#define SM_RED   0
#define SM_MALL  128
#define SM_WP    1152
#define SM_QV    2176
#define SM_QR    4224
#define SM_PMAX  6272
#define SM_PSUM  7296
#define SM_MLOC  8320
#define AW0_OFF  8960     // u32[128][36]: A-hi -> W-hi
#define AW1_OFF  27392    // u32[128][36]: A-lo -> W-lo
#define Q0_OFF   45824    // u16[64][136]: qry k-major (rn-rounded fp16, GEMM2)
#define B0_OFF   45824    // u32[64][36] GEMM1 B-hi (aliases Q0, dead before GEMM2)
#define B1_OFF   55040    // GEMM1 B-lo (ends 64256)
#define EP_OFF   64512    // f32[32][132] epilogue bounce
#define SMEM_BYTES 81408

// fast fp32 -> fp16 hi/lo split: truncate mantissa to 10 bits (exact in fp16),
// residual lo = f - hi is exact in fp32; one f16x2 cvt packs a pair.
__device__ __forceinline__ float hif(float f) {
    return __uint_as_float(__float_as_uint(f) & 0xFFFFE000u);
}
__device__ __forceinline__ uint32_t pk2h(float lo, float hi) {
    uint32_t r;
    asm("cvt.rn.f16x2.f32 %0, %1, %2;" : "=r"(r) : "f"(hi), "f"(lo));
    return r;
}
__device__ __forceinline__ void cvt4(float4 v, uint32_t& h01, uint32_t& h23,
                                     uint32_t& l01, uint32_t& l23) {
    float hx = hif(v.x), hy = hif(v.y), hz = hif(v.z), hw = hif(v.w);
    h01 = pk2h(hx, hy);
    h23 = pk2h(hz, hw);
    l01 = pk2h(v.x - hx, v.y - hy);
    l23 = pk2h(v.z - hz, v.w - hw);
}
__device__ __forceinline__ void mma16816(float* d, const uint32_t* a, const uint32_t* b) {
    asm volatile(
        "mma.sync.aligned.m16n8k16.row.col.f32.f16.f16.f32 "
        "{%0,%1,%2,%3}, {%4,%5,%6,%7}, {%8,%9}, {%0,%1,%2,%3};"
        : "+f"(d[0]), "+f"(d[1]), "+f"(d[2]), "+f"(d[3])
        : "r"(a[0]), "r"(a[1]), "r"(a[2]), "r"(a[3]), "r"(b[0]), "r"(b[1]));
}
__device__ __forceinline__ void ldsm4(uint32_t& r0, uint32_t& r1, uint32_t& r2,
                                      uint32_t& r3, uint32_t addr) {
    asm volatile("ldmatrix.sync.aligned.m8n8.x4.shared.b16 {%0,%1,%2,%3}, [%4];"
                 : "=r"(r0), "=r"(r1), "=r"(r2), "=r"(r3) : "r"(addr));
}
__device__ __forceinline__ void ldsm4t(uint32_t& r0, uint32_t& r1, uint32_t& r2,
                                       uint32_t& r3, uint32_t addr) {
    asm volatile("ldmatrix.sync.aligned.m8n8.x4.trans.shared.b16 {%0,%1,%2,%3}, [%4];"
                 : "=r"(r0), "=r"(r1), "=r"(r2), "=r"(r3) : "r"(addr));
}
__device__ __forceinline__ uint32_t ctarank() {
    uint32_t r; asm("mov.u32 %0, %%cluster_ctarank;" : "=r"(r)); return r;
}
__device__ __forceinline__ uint32_t mapa_sh(uint32_t a, uint32_t rk) {
    uint32_t o; asm("mapa.shared::cluster.u32 %0, %1, %2;" : "=r"(o) : "r"(a), "r"(rk));
    return o;
}
__device__ __forceinline__ void st_remote_f32(uint32_t a, float v) {
    asm volatile("st.shared::cluster.f32 [%0], %1;" :: "r"(a), "f"(v) : "memory");
}
__device__ __forceinline__ void st_remote_f32x2(uint32_t a, float v0, float v1) {
    asm volatile("st.shared::cluster.v2.f32 [%0], {%1, %2};"
                 :: "r"(a), "f"(v0), "f"(v1) : "memory");
}
#define CLUSTER_SYNC() do { \
    asm volatile("barrier.cluster.arrive.aligned;" ::: "memory"); \
    asm volatile("barrier.cluster.wait.aligned;" ::: "memory"); } while (0)

__global__ void __launch_bounds__(NT, 2) __cluster_dims__(2, 1, 1)
ce_hmma15(const float* __restrict__ enc, float* __restrict__ out)
{
    extern __shared__ char smc[];
    float* red   = (float*)(smc + SM_RED);
    float* m_all = (float*)(smc + SM_MALL);
    float* wp    = (float*)(smc + SM_WP);
    float* qvec  = (float*)(smc + SM_QV);
    float* qrecv = (float*)(smc + SM_QR);
    float* pmax  = (float*)(smc + SM_PMAX);
    float* psum  = (float*)(smc + SM_PSUM);
    float* m_loc = (float*)(smc + SM_MLOC);
    uint32_t* AW0 = (uint32_t*)(smc + AW0_OFF);
    uint32_t* AW1 = (uint32_t*)(smc + AW1_OFF);
    uint32_t* B0s = (uint32_t*)(smc + B0_OFF);
    uint32_t* B1s = (uint32_t*)(smc + B1_OFF);
    float* EP  = (float*)(smc + EP_OFF);

    uint32_t sm0;
    { uint64_t t = __cvta_generic_to_shared(smc); sm0 = (uint32_t)t; }

    const int tid  = threadIdx.x;
    const int lane = tid & 31;
    const int warp = tid >> 5;
    const int lq   = lane & 3;
    const int lr   = lane >> 2;
    const int b    = blockIdx.x >> 1;
    const uint32_t rank = ctarank();
    const int p_base = (int)rank * PLC;

    const float* enc_b = enc + (size_t)b * QE * DIM;
    const float* arow_g = enc_b + (size_t)p_base * DIM;
    const float* qry_g  = enc_b + (size_t)PL * DIM;

    const int wm = warp >> 1, wn = warp & 1;
    const int m0 = wm * 32, n0 = wn * 32;

    // ldmatrix per-thread address offsets
    const uint32_t lA = (uint32_t)((((lane >> 3) & 1) * 8 + (lane & 7)) * 144
                                   + ((lane >> 4) * 8) * 2);
    const uint32_t lB = (uint32_t)((((lane >> 4) << 3) + (lane & 7)) * 144
                                   + (((lane >> 3) & 1) * 8) * 2);
    // trans-LDSM lane map for k-major Q
    const uint32_t lT = (uint32_t)(((lane & 7) + ((lane >> 3) & 1) * 8) * QSTB
                                   + (lane >> 4) * 16);
    const uint32_t aA0 = sm0 + AW0_OFF + (uint32_t)(m0 * 144) + lA;
    const uint32_t aA1 = sm0 + AW1_OFF + (uint32_t)(m0 * 144) + lA;
    const uint32_t aB0g1 = sm0 + B0_OFF + (uint32_t)(n0 * 144) + lB;
    const uint32_t aB1g1 = sm0 + B1_OFF + (uint32_t)(n0 * 144) + lB;
    const uint32_t aQ0 = sm0 + Q0_OFF + (uint32_t)(wn * 64 * 2) + lT;

    // ================= GEMM1: sim[128x64] = A @ qry^T, K=512 =================
    float4 pa[8], pb[4];
    #pragma unroll
    for (int k = 0; k < 8; k++) {
        int idx = tid + 256 * k, r = idx >> 4, c4 = idx & 15;
        pa[k] = *(const float4*)&arow_g[(size_t)r * DIM + c4 * 4];
    }
    #pragma unroll
    for (int k = 0; k < 4; k++) {
        int idx = tid + 256 * k, q = idx >> 4, c4 = idx & 15;
        pb[k] = (q < QL) ? *(const float4*)&qry_g[(size_t)q * DIM + c4 * 4]
                         : make_float4(0.f, 0.f, 0.f, 0.f);
    }

    float acc[2][4][4];
    #pragma unroll
    for (int i = 0; i < 2; i++)
        #pragma unroll
        for (int j = 0; j < 4; j++)
            #pragma unroll
            for (int k = 0; k < 4; k++) acc[i][j][k] = 0.f;

    for (int ch = 0; ch < 8; ch++) {
        #pragma unroll
        for (int k = 0; k < 8; k++) {
            int idx = tid + 256 * k, r = idx >> 4, c4 = idx & 15;
            uint32_t h01, h23, l01, l23;
            cvt4(pa[k], h01, h23, l01, l23);
            int o = r * MST + c4 * 2;
            AW0[o] = h01; AW0[o + 1] = h23;
            AW1[o] = l01; AW1[o + 1] = l23;
        }
        #pragma unroll
        for (int k = 0; k < 4; k++) {
            int idx = tid + 256 * k, q = idx >> 4, c4 = idx & 15;
            uint32_t h01, h23, l01, l23;
            cvt4(pb[k], h01, h23, l01, l23);
            int o = q * MST + c4 * 2;
            B0s[o] = h01; B0s[o + 1] = h23;
            B1s[o] = l01; B1s[o + 1] = l23;
        }
        __syncthreads();

        if (ch < 7) {
            const int d0 = (ch + 1) * 64;
            #pragma unroll
            for (int k = 0; k < 8; k++) {
                int idx = tid + 256 * k, r = idx >> 4, c4 = idx & 15;
                pa[k] = *(const float4*)&arow_g[(size_t)r * DIM + d0 + c4 * 4];
            }
            #pragma unroll
            for (int k = 0; k < 4; k++) {
                int idx = tid + 256 * k, q = idx >> 4, c4 = idx & 15;
                pb[k] = (q < QL) ? *(const float4*)&qry_g[(size_t)q * DIM + d0 + c4 * 4]
                                 : make_float4(0.f, 0.f, 0.f, 0.f);
            }
        }

        #pragma unroll
        for (int ks = 0; ks < 4; ks++) {
            uint32_t bh[4][2], bl[4][2];
            #pragma unroll
            for (int pp = 0; pp < 2; pp++) {
                ldsm4(bh[2*pp][0], bh[2*pp][1], bh[2*pp+1][0], bh[2*pp+1][1],
                      aB0g1 + pp * (16 * 144) + ks * 32);
                ldsm4(bl[2*pp][0], bl[2*pp][1], bl[2*pp+1][0], bl[2*pp+1][1],
                      aB1g1 + pp * (16 * 144) + ks * 32);
            }
            #pragma unroll
            for (int mt = 0; mt < 2; mt++) {
                uint32_t ah[4], al[4];
                ldsm4(ah[0], ah[1], ah[2], ah[3], aA0 + mt * (16 * 144) + ks * 32);
                ldsm4(al[0], al[1], al[2], al[3], aA1 + mt * (16 * 144) + ks * 32);
                #pragma unroll
                for (int nt = 0; nt < 4; nt++) {
                    mma16816(acc[mt][nt], ah, bh[nt]);
                    mma16816(acc[mt][nt], ah, bl[nt]);
                    mma16816(acc[mt][nt], al, bh[nt]);
                }
            }
        }
        __syncthreads();
    }

    // ====== fragment-resident softmax over q; W -> AW0/AW1 as fp16 hi/lo ======
    {
        float mx[2][2];
        #pragma unroll
        for (int mt = 0; mt < 2; mt++) { mx[mt][0] = -3.4e38f; mx[mt][1] = -3.4e38f; }
        #pragma unroll
        for (int mt = 0; mt < 2; mt++)
            #pragma unroll
            for (int nt = 0; nt < 4; nt++) {
                int col = n0 + nt * 8 + lq * 2;
                if (col < QL) {
                    mx[mt][0] = fmaxf(mx[mt][0], acc[mt][nt][0]);
                    mx[mt][1] = fmaxf(mx[mt][1], acc[mt][nt][2]);
                }
                if (col + 1 < QL) {
                    mx[mt][0] = fmaxf(mx[mt][0], acc[mt][nt][1]);
                    mx[mt][1] = fmaxf(mx[mt][1], acc[mt][nt][3]);
                }
            }
        #pragma unroll
        for (int mt = 0; mt < 2; mt++)
            #pragma unroll
            for (int rh = 0; rh < 2; rh++) {
                mx[mt][rh] = fmaxf(mx[mt][rh], __shfl_xor_sync(0xffffffffu, mx[mt][rh], 1));
                mx[mt][rh] = fmaxf(mx[mt][rh], __shfl_xor_sync(0xffffffffu, mx[mt][rh], 2));
            }
        if (lq == 0) {
            #pragma unroll
            for (int mt = 0; mt < 2; mt++)
                #pragma unroll
                for (int rh = 0; rh < 2; rh++)
                    pmax[wn * 128 + m0 + mt * 16 + rh * 8 + lr] = mx[mt][rh];
        }
        __syncthreads();
        float fmx[2][2];
        #pragma unroll
        for (int mt = 0; mt < 2; mt++)
            #pragma unroll
            for (int rh = 0; rh < 2; rh++) {
                int row = m0 + mt * 16 + rh * 8 + lr;
                fmx[mt][rh] = fmaxf(pmax[row], pmax[128 + row]);
                if (wn == 0 && lq == 0) m_loc[row] = fmx[mt][rh];
            }
        float sm[2][2];
        #pragma unroll
        for (int mt = 0; mt < 2; mt++) { sm[mt][0] = 0.f; sm[mt][1] = 0.f; }
        #pragma unroll
        for (int mt = 0; mt < 2; mt++)
            #pragma unroll
            for (int nt = 0; nt < 4; nt++) {
                int col = n0 + nt * 8 + lq * 2;
                float e0 = (col     < QL) ? expf(acc[mt][nt][0] - fmx[mt][0]) : 0.f;
                float e1 = (col + 1 < QL) ? expf(acc[mt][nt][1] - fmx[mt][0]) : 0.f;
                float e2 = (col     < QL) ? expf(acc[mt][nt][2] - fmx[mt][1]) : 0.f;
                float e3 = (col + 1 < QL) ? expf(acc[mt][nt][3] - fmx[mt][1]) : 0.f;
                acc[mt][nt][0] = e0; acc[mt][nt][1] = e1;
                acc[mt][nt][2] = e2; acc[mt][nt][3] = e3;
                sm[mt][0] += e0 + e1; sm[mt][1] += e2 + e3;
            }
        #pragma unroll
        for (int mt = 0; mt < 2; mt++)
            #pragma unroll
            for (int rh = 0; rh < 2; rh++) {
                sm[mt][rh] += __shfl_xor_sync(0xffffffffu, sm[mt][rh], 1);
                sm[mt][rh] += __shfl_xor_sync(0xffffffffu, sm[mt][rh], 2);
            }
        if (lq == 0) {
            #pragma unroll
            for (int mt = 0; mt < 2; mt++)
                #pragma unroll
                for (int rh = 0; rh < 2; rh++)
                    psum[wn * 128 + m0 + mt * 16 + rh * 8 + lr] = sm[mt][rh];
        }
        __syncthreads();
        #pragma unroll
        for (int mt = 0; mt < 2; mt++) {
            float inv0, inv1;
            {
                int r0 = m0 + mt * 16 + lr;
                inv0 = 1.f / (psum[r0] + psum[128 + r0]);
                inv1 = 1.f / (psum[r0 + 8] + psum[128 + r0 + 8]);
            }
            #pragma unroll
            for (int nt = 0; nt < 4; nt++) {
                int cw = wn * 16 + nt * 4 + lq;
                int r0 = (m0 + mt * 16 + lr) * MST;
                int r1 = r0 + 8 * MST;
                float wa = acc[mt][nt][0] * inv0, wb = acc[mt][nt][1] * inv0;
                float ha = hif(wa), hb = hif(wb);
                AW0[r0 + cw] = pk2h(ha, hb);
                AW1[r0 + cw] = pk2h(wa - ha, wb - hb);
                float wc = acc[mt][nt][2] * inv1, wd = acc[mt][nt][3] * inv1;
                float hc = hif(wc), hd = hif(wd);
                AW0[r1 + cw] = pk2h(hc, hd);
                AW1[r1 + cw] = pk2h(wc - hc, wd - hd);
            }
        }
    }
    __syncthreads();

    // ====== exchange per-row maxes with partner CTA (DSMEM) ======
    if (tid < PLC) {
        float v = m_loc[tid];
        m_all[p_base + tid] = v;
        st_remote_f32(mapa_sh(sm0 + SM_MALL + (uint32_t)(p_base + tid) * 4, rank ^ 1u), v);
    }
    CLUSTER_SYNC();

    // ====== softmax over p of max_sim -> wp[200] ======
    {
        float v = (tid < PL) ? m_all[tid] : -3.4e38f;
        float mv = v;
        #pragma unroll
        for (int o = 16; o > 0; o >>= 1) mv = fmaxf(mv, __shfl_xor_sync(0xffffffffu, mv, o));
        if (lane == 0) red[warp] = mv;
        __syncthreads();
        if (warp == 0) {
            float x = (lane < 8) ? red[lane] : -3.4e38f;
            #pragma unroll
            for (int o = 4; o > 0; o >>= 1) x = fmaxf(x, __shfl_xor_sync(0xffffffffu, x, o));
            if (lane == 0) red[8] = x;
        }
        __syncthreads();
        float gmax = red[8];
        float e = (tid < PL) ? expf(v - gmax) : 0.f;
        float sv = e;
        #pragma unroll
        for (int o = 16; o > 0; o >>= 1) sv += __shfl_xor_sync(0xffffffffu, sv, o);
        if (lane == 0) red[16 + warp] = sv;
        __syncthreads();
        if (warp == 0) {
            float x = (lane < 8) ? red[16 + lane] : 0.f;
            #pragma unroll
            for (int o = 4; o > 0; o >>= 1) x += __shfl_xor_sync(0xffffffffu, x, o);
            if (lane == 0) red[9] = x;
        }
        __syncthreads();
        if (tid < PL) wp[tid] = e / red[9];
    }
    __syncthreads();

    // ====== partial q2c over own 100 rows (float2/thread); exchange; qvec = sum ======
    {
        float2 qa = make_float2(0.f, 0.f);
        #pragma unroll 4
        for (int i = 0; i < PLC; i++) {
            float w = wp[p_base + i];
            float2 a = *(const float2*)&arow_g[(size_t)i * DIM + 2 * tid];
            qa.x += w * a.x;
            qa.y += w * a.y;
        }
        st_remote_f32x2(mapa_sh(sm0 + SM_QR + (uint32_t)(2 * tid) * 4, rank ^ 1u),
                        qa.x, qa.y);
        CLUSTER_SYNC();
        qvec[2 * tid]     = qa.x + qrecv[2 * tid];
        qvec[2 * tid + 1] = qa.y + qrecv[2 * tid + 1];
    }
    __syncthreads();

    // ================= GEMM2: c2q = W @ qry + epilogue (4 d-chunks) =================
    // 2-term decomposition: (W_hi + W_lo) @ qry_fp16(rn). Dropped W_hi @ qry_lo term
    // contributes <= 2^-11 relative on c2q segments — within the 1e-3 budget.
    const float4* ctx4 = (const float4*)enc_b;
    const float4* qv4  = (const float4*)qvec;
    float4* out4 = (float4*)out + (size_t)b * PL * 512;

    #pragma unroll 1
    for (int dch = 0; dch < 4; dch++) {
        // ---- store qry chunk k-major as rn-rounded fp16 (single part) ----
        #pragma unroll
        for (int k = 0; k < 8; k++) {
            int idx = tid + 256 * k, q = idx >> 5, c4 = idx & 31;
            float4 v = (q < QL) ? *(const float4*)&qry_g[(size_t)q * DIM + dch * 128 + c4 * 4]
                                : make_float4(0.f, 0.f, 0.f, 0.f);
            uint32_t* p0 = (uint32_t*)(smc + Q0_OFF + q * QSTB + c4 * 8);
            p0[0] = pk2h(v.x, v.y);
            p0[1] = pk2h(v.z, v.w);
        }
        __syncthreads();

        // ---- MMA: [128 p] x [128 d], K=64 (q); B via trans-LDSM, 2 terms ----
        float a2[2][8][4];
        #pragma unroll
        for (int i = 0; i < 2; i++)
            #pragma unroll
            for (int j = 0; j < 8; j++)
                #pragma unroll
                for (int k = 0; k < 4; k++) a2[i][j][k] = 0.f;

        #pragma unroll
        for (int ks = 0; ks < 4; ks++) {
            uint32_t ah[2][4], al[2][4];
            #pragma unroll
            for (int mt = 0; mt < 2; mt++) {
                ldsm4(ah[mt][0], ah[mt][1], ah[mt][2], ah[mt][3],
                      aA0 + mt * (16 * 144) + ks * 32);
                ldsm4(al[mt][0], al[mt][1], al[mt][2], al[mt][3],
                      aA1 + mt * (16 * 144) + ks * 32);
            }
            #pragma unroll
            for (int pp = 0; pp < 4; pp++) {
                uint32_t bh[2][2];
                ldsm4t(bh[0][0], bh[0][1], bh[1][0], bh[1][1],
                       aQ0 + ks * (16 * QSTB) + pp * 32);
                #pragma unroll
                for (int h = 0; h < 2; h++) {
                    int nt = pp * 2 + h;
                    #pragma unroll
                    for (int mt = 0; mt < 2; mt++) {
                        mma16816(a2[mt][nt], ah[mt], bh[h]);
                        mma16816(a2[mt][nt], al[mt], bh[h]);
                    }
                }
            }
        }

        // ---- epilogue: 4 groups of 32 p-rows bounced through EP ----
        #pragma unroll 1
        for (int g = 0; g < 4; g++) {
            __syncthreads();
            if (wm == g) {
                #pragma unroll
                for (int mt = 0; mt < 2; mt++)
                    #pragma unroll
                    for (int nt = 0; nt < 8; nt++) {
                        int col = wn * 64 + nt * 8 + lq * 2;
                        *(float2*)&EP[(mt * 16 + lr) * EPST + col] =
                            make_float2(a2[mt][nt][0], a2[mt][nt][1]);
                        *(float2*)&EP[(mt * 16 + lr + 8) * EPST + col] =
                            make_float2(a2[mt][nt][2], a2[mt][nt][3]);
                    }
            }
            __syncthreads();
            #pragma unroll
            for (int j = 0; j < 4; j++) {
                int p_loc = g * 32 + warp * 4 + j;
                if (p_loc < PLC) {
                    int p = p_base + p_loc;
                    int d4 = dch * 32 + lane;
                    float4 cq = *(const float4*)&EP[(warp * 4 + j) * EPST + lane * 4];
                    float4 c  = ctx4[(size_t)p * 128 + d4];
                    float4 qc = qv4[d4];
                    float4* ob = out4 + (size_t)p * 512 + d4;
                    __stcs(ob,       c);
                    __stcs(ob + 128, cq);
                    __stcs(ob + 256, make_float4(c.x * cq.x, c.y * cq.y,
                                                 c.z * cq.z, c.w * cq.w));
                    __stcs(ob + 384, make_float4(c.x * qc.x, c.y * qc.y,
                                                 c.z * qc.z, c.w * qc.w));
                }
            }
        }
    }
}

extern "C" void kernel_launch(void* const* d_in, const int* in_sizes, int n_in,
                              void* d_out, int out_size)
{
    const float* enc = (const float*)d_in[0];
    float* out = (float*)d_out;
    cudaFuncSetAttribute(ce_hmma15,
                         cudaFuncAttributeMaxDynamicSharedMemorySize, SMEM_BYTES);
    ce_hmma15<<<NB * 2, NT, SMEM_BYTES>>>(enc, out);
}